// round 1
// baseline (speedup 1.0000x reference)
#include <cuda_runtime.h>
#include <math.h>

#define BS 16
#define QN 900
#define NC 92
#define TN 256
#define NQT (BS*QN)        // 14400 total queries
#define NT  (BS*TN)        // 4096 total targets
#define C_ELEMS (NQT*NT)   // 58,982,400

// ---------------- scratch (static device globals; no cudaMalloc allowed) ----
__device__ float  g_prob[NQT*NC];     // softmax probs          5.3 MB
__device__ float  g_predf[NQT*12];    // cx,cy,w,h,x0,y0,x1,y1,area,pad  675 KB
__device__ float  g_tgtf[NT*12];      // same for targets       192 KB
__device__ int    g_tlab[NT];
__device__ double g_D[BS*TN*QN];      // per-batch cost slice, transposed [b][t][q], fp64  29.5 MB

// ---------------- prep: box xyxy + area for preds and targets ---------------
__global__ void prep_boxes_k(const float* __restrict__ pb,
                             const float* __restrict__ tb,
                             const int*   __restrict__ tl) {
    int i = blockIdx.x * blockDim.x + threadIdx.x;
    if (i < NQT) {
        float cx = pb[i*4+0], cy = pb[i*4+1], w = pb[i*4+2], h = pb[i*4+3];
        float x0 = cx - 0.5f*w, y0 = cy - 0.5f*h, x1 = cx + 0.5f*w, y1 = cy + 0.5f*h;
        float* o = &g_predf[i*12];
        o[0]=cx; o[1]=cy; o[2]=w; o[3]=h;
        o[4]=x0; o[5]=y0; o[6]=x1; o[7]=y1;
        o[8]=(x1-x0)*(y1-y0);
    }
    if (i < NT) {
        float cx = tb[i*4+0], cy = tb[i*4+1], w = tb[i*4+2], h = tb[i*4+3];
        float x0 = cx - 0.5f*w, y0 = cy - 0.5f*h, x1 = cx + 0.5f*w, y1 = cy + 0.5f*h;
        float* o = &g_tgtf[i*12];
        o[0]=cx; o[1]=cy; o[2]=w; o[3]=h;
        o[4]=x0; o[5]=y0; o[6]=x1; o[7]=y1;
        o[8]=(x1-x0)*(y1-y0);
        g_tlab[i] = tl[i];
    }
}

// ---------------- softmax: one warp per row of 92 logits --------------------
__global__ void softmax_k(const float* __restrict__ logits) {
    int warp = (blockIdx.x * blockDim.x + threadIdx.x) >> 5;
    int lane = threadIdx.x & 31;
    if (warp >= NQT) return;
    const float* row = logits + warp * NC;
    float v0 = row[lane];
    float v1 = row[lane + 32];
    float v2 = (lane + 64 < NC) ? row[lane + 64] : -INFINITY;
    float m = fmaxf(v0, fmaxf(v1, v2));
    #pragma unroll
    for (int o = 16; o; o >>= 1) m = fmaxf(m, __shfl_xor_sync(0xffffffffu, m, o));
    float e0 = expf(v0 - m), e1 = expf(v1 - m), e2 = expf(v2 - m); // exp(-inf)=0
    float s = e0 + e1 + e2;
    #pragma unroll
    for (int o = 16; o; o >>= 1) s += __shfl_xor_sync(0xffffffffu, s, o);
    float* op = g_prob + warp * NC;
    op[lane]      = e0 / s;
    op[lane + 32] = e1 / s;
    if (lane + 64 < NC) op[lane + 64] = e2 / s;
}

// ---------------- fused cost matrix: 16 queries x 256 targets per block -----
__global__ void __launch_bounds__(256) cost_k(float* __restrict__ outC) {
    int jtile = blockIdx.x & 15;        // 4096/256 target tiles
    int itile = blockIdx.x >> 4;        // 14400/16 query tiles
    int tid   = threadIdx.x;
    int jg    = (jtile << 8) + tid;     // global target index (= column)
    int i0    = itile * 16;

    __shared__ float sprob[16 * NC];
    __shared__ float spred[16 * 12];
    for (int k = tid; k < 16 * NC; k += 256) sprob[k] = g_prob[i0 * NC + k];
    for (int k = tid; k < 16 * 12; k += 256) spred[k] = g_predf[i0 * 12 + k];
    __syncthreads();

    // target data lives in registers for all 16 queries
    const float4* tf = (const float4*)&g_tgtf[jg * 12];
    float4 tc = tf[0];                  // cx cy w h
    float4 txy = tf[1];                 // x0 y0 x1 y1
    float  tarea = g_tgtf[jg * 12 + 8];
    int    lab   = g_tlab[jg];
    int    jb    = jg >> 8;             // batch owning this target
    int    jt    = jg & 255;

    #pragma unroll
    for (int ii = 0; ii < 16; ii++) {
        int i = i0 + ii;
        float4 pc  = *(const float4*)&spred[ii * 12];
        float4 pxy = *(const float4*)&spred[ii * 12 + 4];
        float  parea = spred[ii * 12 + 8];
        float  prob  = sprob[ii * NC + lab];

        float l1 = fabsf(pc.x - tc.x) + fabsf(pc.y - tc.y)
                 + fabsf(pc.z - tc.z) + fabsf(pc.w - tc.w);

        float ltx = fmaxf(pxy.x, txy.x), lty = fmaxf(pxy.y, txy.y);
        float rbx = fminf(pxy.z, txy.z), rby = fminf(pxy.w, txy.w);
        float iw = fmaxf(rbx - ltx, 0.0f), ih = fmaxf(rby - lty, 0.0f);
        float inter = iw * ih;
        float uni = parea + tarea - inter;
        float iou = inter / uni;
        float ex0 = fminf(pxy.x, txy.x), ey0 = fminf(pxy.y, txy.y);
        float ex1 = fmaxf(pxy.z, txy.z), ey1 = fmaxf(pxy.w, txy.w);
        float ew = fmaxf(ex1 - ex0, 0.0f), eh = fmaxf(ey1 - ey0, 0.0f);
        float earea = ew * eh;
        float giou = iou - (earea - uni) / earea;

        float c = 5.0f * l1 - prob - 2.0f * giou;
        outC[i * NT + jg] = c;

        int b = i / QN;
        if (b == jb) {
            int q = i - b * QN;
            g_D[((jb << 8) + jt) * QN + q] = (double)c;
        }
    }
}

// ---------------- Jonker-Volgenant LSA, fp64, one block per batch -----------
__global__ void __launch_bounds__(256) lsa_k(float* __restrict__ out) {
    const int b   = blockIdx.x;
    const int tid = threadIdx.x;
    const double* Db = g_D + (size_t)b * TN * QN;   // [t][q]

    __shared__ double sv[QN + 1];
    __shared__ double sminv[QN + 1];
    __shared__ double su[TN + 1];
    __shared__ int    sp[QN + 1];
    __shared__ int    sway[QN + 1];
    __shared__ unsigned char sused[QN + 1];
    __shared__ double wval[8];
    __shared__ int    widx[8];
    __shared__ int    sj0;
    __shared__ double sdelta;
    __shared__ int    sdone;

    const double DINF = __longlong_as_double(0x7ff0000000000000LL);

    for (int j = tid; j <= QN; j += 256) { sv[j] = 0.0; sp[j] = 0; }
    for (int t = tid; t <= TN; t += 256) su[t] = 0.0;
    __syncthreads();

    for (int i = 1; i <= TN; i++) {
        for (int j = tid; j <= QN; j += 256) { sminv[j] = DINF; sway[j] = 0; sused[j] = 0; }
        if (tid == 0) { sp[0] = i; sj0 = 0; }
        __syncthreads();

        while (true) {
            int j0 = sj0;
            if (tid == 0) sused[j0] = 1;
            __syncthreads();

            int i0 = sp[j0];
            double ui0 = su[i0];
            const double* row = Db + (size_t)(i0 - 1) * QN;

            double bv = DINF; int bj = QN + 1;
            for (int j = 1 + tid; j <= QN; j += 256) {
                if (!sused[j]) {
                    double cur = (row[j - 1] - ui0) - sv[j];
                    if (cur < sminv[j]) { sminv[j] = cur; sway[j] = j0; }
                    double mv = sminv[j];
                    if (mv < bv) { bv = mv; bj = j; }
                }
            }
            #pragma unroll
            for (int o = 16; o; o >>= 1) {
                double ov = __shfl_down_sync(0xffffffffu, bv, o);
                int    oj = __shfl_down_sync(0xffffffffu, bj, o);
                if (ov < bv || (ov == bv && oj < bj)) { bv = ov; bj = oj; }
            }
            if ((tid & 31) == 0) { wval[tid >> 5] = bv; widx[tid >> 5] = bj; }
            __syncthreads();
            if (tid == 0) {
                double v = wval[0]; int jj = widx[0];
                #pragma unroll
                for (int w = 1; w < 8; w++)
                    if (wval[w] < v || (wval[w] == v && widx[w] < jj)) { v = wval[w]; jj = widx[w]; }
                sdelta = v; sj0 = jj; sdone = (sp[jj] == 0);
            }
            __syncthreads();

            double delta = sdelta;
            for (int j = tid; j <= QN; j += 256) {
                if (sused[j]) {
                    su[sp[j]] += delta;          // distinct sp among used -> no conflict
                    if (j) sv[j] -= delta;
                } else {
                    sminv[j] -= delta;
                }
            }
            __syncthreads();
            if (sdone) break;
        }

        if (tid == 0) {
            int j0 = sj0;
            while (j0) { int j1 = sway[j0]; sp[j0] = sp[j1]; j0 = j1; }
        }
        __syncthreads();
    }

    if (tid == 0) {
        float* rows = out + C_ELEMS + b * TN;
        float* cols = out + C_ELEMS + NT + b * TN;
        int k = 0;
        for (int j = 1; j <= QN; j++) {
            if (sp[j]) { rows[k] = (float)(j - 1); cols[k] = (float)(sp[j] - 1); k++; }
        }
    }
}

// ---------------- launch -----------------------------------------------------
extern "C" void kernel_launch(void* const* d_in, const int* in_sizes, int n_in,
                              void* d_out, int out_size) {
    const float* logits = (const float*)d_in[0];   // [16,900,92]
    const float* pboxes = (const float*)d_in[1];   // [16,900,4]
    const int*   tlab   = (const int*)  d_in[2];   // [4096] int32
    const float* tbox   = (const float*)d_in[3];   // [4096,4]
    float* out = (float*)d_out;                    // C | rows | cols

    prep_boxes_k<<<(NQT + 255) / 256, 256>>>(pboxes, tbox, tlab);
    softmax_k<<<(NQT * 32 + 255) / 256, 256>>>(logits);
    cost_k<<<14400, 256>>>(out);
    lsa_k<<<BS, 256>>>(out);
}